// round 14
// baseline (speedup 1.0000x reference)
#include <cuda_runtime.h>
#include <cuda_fp16.h>
#include <cstdint>
#include <math.h>

#define B_SZ   8192
#define LEADS  12
#define FIN    512
#define HID    256
#define E3     768
#define MROWS  (B_SZ * LEADS)   // 98304

// ---------------- static scratch ----------------
__device__ float g_A[LEADS * LEADS];
__device__ __half g_qkv[(size_t)MROWS * E3];
__device__ __half g_buf1[(size_t)MROWS * HID];
__device__ __half g_buf2[(size_t)MROWS * HID];
__device__ __half g_buf3[(size_t)MROWS * HID];

__device__ __half g_W1[HID * FIN];
__device__ __half g_W2[HID * HID];
__device__ __half g_W3[HID * HID];
__device__ __half g_Iw[E3 * HID];
__device__ __half g_Ow[HID * HID];

// ---------------- helpers ----------------
__device__ __forceinline__ uint32_t smem_u32(const void* p) {
    uint32_t a;
    asm("{ .reg .u64 t; cvta.to.shared.u64 t, %1; cvt.u32.u64 %0, t; }" : "=r"(a) : "l"(p));
    return a;
}
__device__ __forceinline__ void ldsm4(uint32_t& r0, uint32_t& r1, uint32_t& r2, uint32_t& r3,
                                      uint32_t a) {
    asm volatile("ldmatrix.sync.aligned.m8n8.x4.shared.b16 {%0,%1,%2,%3}, [%4];"
                 : "=r"(r0), "=r"(r1), "=r"(r2), "=r"(r3) : "r"(a));
}
__device__ __forceinline__ void ldsm4t(uint32_t& r0, uint32_t& r1, uint32_t& r2, uint32_t& r3,
                                       uint32_t a) {
    asm volatile("ldmatrix.sync.aligned.m8n8.x4.trans.shared.b16 {%0,%1,%2,%3}, [%4];"
                 : "=r"(r0), "=r"(r1), "=r"(r2), "=r"(r3) : "r"(a));
}
__device__ __forceinline__ void mma16816(float* c, const uint32_t* a, const uint32_t* b) {
    asm volatile("mma.sync.aligned.m16n8k16.row.col.f32.f16.f16.f32 "
                 "{%0,%1,%2,%3}, {%4,%5,%6,%7}, {%8,%9}, {%0,%1,%2,%3};"
                 : "+f"(c[0]), "+f"(c[1]), "+f"(c[2]), "+f"(c[3])
                 : "r"(a[0]), "r"(a[1]), "r"(a[2]), "r"(a[3]), "r"(b[0]), "r"(b[1]));
}
__device__ __forceinline__ void cp16(uint32_t d, const void* g) {
    asm volatile("cp.async.ca.shared.global [%0], [%1], 16;" :: "r"(d), "l"(g));
}
#define CP_COMMIT  asm volatile("cp.async.commit_group;" ::: "memory")
#define CP_WAIT(n) asm volatile("cp.async.wait_group %0;" :: "n"(n) : "memory")

// ---------------- prep: A_norm + weight converts only (no x pass) ----------------
#define PREP_W1   131072
#define PREP_W2   (PREP_W1 + 65536)
#define PREP_W3   (PREP_W2 + 65536)
#define PREP_IW   (PREP_W3 + 196608)
#define PREP_OW   (PREP_IW + 65536)
#define PREP_BLOCKS  (PREP_OW / 256)   // 2048

__global__ void k_prep(const float* __restrict__ W1,
                       const float* __restrict__ W2, const float* __restrict__ W3,
                       const float* __restrict__ inW, const float* __restrict__ outW)
{
    size_t gid = (size_t)blockIdx.x * blockDim.x + threadIdx.x;
    if (gid == 0) {
        const int ci[18] = {0,0,1,0,1,2,0,1,1,2,6,7,8,9,10,0,1,2};
        const int cj[18] = {1,2,2,3,3,3,4,4,5,5,7,8,9,10,11,6,9,11};
        float A[12][12];
        for (int i = 0; i < 12; i++)
            for (int j = 0; j < 12; j++) A[i][j] = (i == j) ? 1.0f : 0.0f;
        for (int e = 0; e < 18; e++) { A[ci[e]][cj[e]] = 1.0f; A[cj[e]][ci[e]] = 1.0f; }
        float dinv[12];
        for (int i = 0; i < 12; i++) {
            float s = 0.0f;
            for (int j = 0; j < 12; j++) s += A[i][j];
            dinv[i] = 1.0f / sqrtf(s);
        }
        for (int i = 0; i < 12; i++)
            for (int j = 0; j < 12; j++) g_A[i * 12 + j] = dinv[i] * A[i][j] * dinv[j];
    }
    if (gid < PREP_W1) {
        size_t l = gid;
        int k = (int)(l >> 8), n = (int)(l & 255);
        g_W1[n * FIN + k] = __float2half_rn(W1[l]);
        return;
    }
    if (gid < PREP_W2) {
        size_t l = gid - PREP_W1;
        int k = (int)(l >> 8), n = (int)(l & 255);
        g_W2[n * HID + k] = __float2half_rn(W2[l]);
        return;
    }
    if (gid < PREP_W3) {
        size_t l = gid - PREP_W2;
        int k = (int)(l >> 8), n = (int)(l & 255);
        g_W3[n * HID + k] = __float2half_rn(W3[l]);
        return;
    }
    if (gid < PREP_IW) {
        size_t l = gid - PREP_W3;
        g_Iw[l] = __float2half_rn(inW[l]);
        return;
    }
    if (gid < PREP_OW) {
        size_t l = gid - PREP_IW;
        g_Ow[l] = __float2half_rn(outW[l]);
        return;
    }
}

// ---------------- fp16 GEMM core (R8/R12 geometry, unchanged) ----------------
// Block tile 256x128, 256 threads (8 warps 4Mx2N), warp tile 64x64, BK=64.
#define SROW    72
#define B_OFF_H (256 * SROW)
#define STAGE_H (384 * SROW)
#define STAGE_B (STAGE_H * 2)
#define NSTAGE  3
#define SMEM_BYTES (NSTAGE * STAGE_B)

struct GemmCtx {
    int lane, wm, wn;
    int arow, akblk, bn, bkblk, bntoff;
};

__device__ __forceinline__ GemmCtx make_ctx(int tid) {
    GemmCtx g;
    g.lane = tid & 31;
    int w = tid >> 5;
    g.wm = w >> 1;
    g.wn = w & 1;
    g.arow  = (g.lane & 7) | (((g.lane >> 3) & 1) << 3);
    g.akblk = (g.lane >> 4) & 1;
    int bwhich = g.lane >> 3;
    g.bn     = g.lane & 7;
    g.bkblk  = bwhich & 1;
    g.bntoff = bwhich >> 1;
    return g;
}

__device__ __forceinline__ void load_frags(const GemmCtx& g, uint32_t so, int ks,
                                           uint32_t ah[4][4], uint32_t bh[4][4]) {
#pragma unroll
    for (int mt = 0; mt < 4; mt++) {
        uint32_t aoff = so + ((g.wm * 64 + mt * 16 + g.arow) * SROW + ks * 16 + g.akblk * 8) * 2;
        ldsm4(ah[mt][0], ah[mt][1], ah[mt][2], ah[mt][3], aoff);
    }
#pragma unroll
    for (int p = 0; p < 4; p++) {
        int nt = p * 2 + g.bntoff;
        uint32_t boff = so + (B_OFF_H + (g.wn * 64 + nt * 8 + g.bn) * SROW + ks * 16 + g.bkblk * 8) * 2;
        ldsm4(bh[p][0], bh[p][1], bh[p][2], bh[p][3], boff);
    }
}

__device__ __forceinline__ void do_mmas(const uint32_t ah[4][4], const uint32_t bh[4][4],
                                        float c[4][8][4]) {
#pragma unroll
    for (int mt = 0; mt < 4; mt++)
#pragma unroll
        for (int p = 0; p < 4; p++)
#pragma unroll
            for (int h = 0; h < 2; h++)
                mma16816(c[mt][p * 2 + h], ah[mt], &bh[p][h * 2]);
}

template <bool BIAS>
__global__ __launch_bounds__(256, 1) void k_hgemm(
    const __half* __restrict__ A,
    const __half* __restrict__ B,
    const float* __restrict__ bias,
    __half* __restrict__ C,
    int K, int N)
{
    extern __shared__ __half sm[];
    const int tid  = threadIdx.x;
    const int row0 = blockIdx.y * 256;
    const int col0 = blockIdx.x * 128;
    const int NC   = K >> 6;
    const uint32_t sbase = smem_u32(sm);
    GemmCtx g = make_ctx(tid);

    float c[4][8][4];
#pragma unroll
    for (int i = 0; i < 4; i++)
#pragma unroll
        for (int j = 0; j < 8; j++)
#pragma unroll
            for (int q = 0; q < 4; q++) c[i][j][q] = 0.0f;

    const int rr = tid >> 3;
    const int qq = (tid & 7) * 8;
    const __half* Ab = A + (size_t)(row0 + rr) * K + qq;
    const __half* Bb = B + (size_t)(col0 + rr) * K + qq;
    const uint32_t doff = (rr * SROW + qq) * 2;

    auto cpa = [&](int cc) {
        uint32_t st = sbase + (cc % 3) * STAGE_B + doff;
        const __half* Ac = Ab + cc * 64;
        const __half* Bc = Bb + cc * 64;
#pragma unroll
        for (int u = 0; u < 8; u++)
            cp16(st + u * 32 * SROW * 2, Ac + (size_t)(u * 32) * K);
#pragma unroll
        for (int u = 0; u < 4; u++)
            cp16(st + (B_OFF_H + u * 32 * SROW) * 2, Bc + (size_t)(u * 32) * K);
    };

    int npre = NC < 2 ? NC : 2;
    for (int s = 0; s < npre; s++) { cpa(s); CP_COMMIT; }

    uint32_t ah[2][4][4], bh[2][4][4];

    for (int cc = 0; cc < NC; cc++) {
        if (cc + 1 < NC) CP_WAIT(1); else CP_WAIT(0);
        __syncthreads();
        if (cc + 2 < NC) { cpa(cc + 2); CP_COMMIT; }

        uint32_t so = sbase + (cc % 3) * STAGE_B;
        load_frags(g, so, 0, ah[0], bh[0]);
#pragma unroll
        for (int ks = 0; ks < 4; ks++) {
            int cur = ks & 1;
            if (ks < 3) load_frags(g, so, ks + 1, ah[cur ^ 1], bh[cur ^ 1]);
            do_mmas(ah[cur], bh[cur], c);
        }
        __syncthreads();
    }

#pragma unroll
    for (int mt = 0; mt < 4; mt++) {
        int row = row0 + g.wm * 64 + mt * 16 + (g.lane >> 2);
#pragma unroll
        for (int n8 = 0; n8 < 8; n8++) {
            int col = col0 + g.wn * 64 + n8 * 8 + (g.lane & 3) * 2;
            float b0 = 0.0f, b1 = 0.0f;
            if (BIAS) { b0 = bias[col]; b1 = bias[col + 1]; }
            __half2 o0 = __floats2half2_rn(c[mt][n8][0] + b0, c[mt][n8][1] + b1);
            __half2 o1 = __floats2half2_rn(c[mt][n8][2] + b0, c[mt][n8][3] + b1);
            *(__half2*)(C + (size_t)row * N + col)       = o0;
            *(__half2*)(C + (size_t)(row + 8) * N + col) = o1;
        }
    }
}

// ---------------- f32-A GEMM (gcn1): converts x on the fly ----------------
// Block tile 128x128, 256 threads (8 warps 2Mx4N), warp tile 64x32, BK=64.
#define F_B_OFF_H (128 * SROW)
#define F_STAGE_H (256 * SROW)
#define F_STAGE_B (F_STAGE_H * 2)
#define F_SMEM_BYTES (NSTAGE * F_STAGE_B)

__global__ __launch_bounds__(256, 1) void k_hgemm_f32a(
    const float* __restrict__ A,
    const __half* __restrict__ B,
    __half* __restrict__ C,
    int K, int N)
{
    extern __shared__ __half sm[];
    const int tid  = threadIdx.x;
    const int lane = tid & 31;
    const int w    = tid >> 5;
    const int wm   = w >> 2;        // 0..1
    const int wn   = w & 3;         // 0..3
    const int row0 = blockIdx.y * 128;
    const int col0 = blockIdx.x * 128;
    const int NC   = K >> 6;
    const uint32_t sbase = smem_u32(sm);

    const int arow  = (lane & 7) | (((lane >> 3) & 1) << 3);
    const int akblk = (lane >> 4) & 1;
    const int bwhich = lane >> 3;
    const int bn     = lane & 7;
    const int bkblk  = bwhich & 1;
    const int bntoff = bwhich >> 1;

    float c[4][4][4];
#pragma unroll
    for (int i = 0; i < 4; i++)
#pragma unroll
        for (int j = 0; j < 4; j++)
#pragma unroll
            for (int q = 0; q < 4; q++) c[i][j][q] = 0.0f;

    // A fp32 load mapping: 8 float4 per thread per chunk
    const int ar = tid >> 4;           // 0..15
    const int aq = (tid & 15) * 4;     // 0..60 (float cols)
    const float* Af = A + (size_t)(row0 + ar) * K + aq;

    // B cp.async mapping
    const int rr = tid >> 3;           // 0..31
    const int qq = (tid & 7) * 8;
    const __half* Bb = B + (size_t)(col0 + rr) * K + qq;
    const uint32_t bdoff = (F_B_OFF_H + rr * SROW + qq) * 2;

    float4 pa[8];

    auto ldgA = [&](int cc) {
#pragma unroll
        for (int u = 0; u < 8; u++)
            pa[u] = *(const float4*)(Af + (size_t)(u * 16) * K + cc * 64);
    };
    auto stsA = [&](int cc) {
        __half* st = sm + (cc % 3) * F_STAGE_H + ar * SROW + aq;
#pragma unroll
        for (int u = 0; u < 8; u++) {
            __half2* d = (__half2*)(st + u * 16 * SROW);
            d[0] = __floats2half2_rn(pa[u].x, pa[u].y);
            d[1] = __floats2half2_rn(pa[u].z, pa[u].w);
        }
    };
    auto cpaB = [&](int cc) {
        uint32_t st = sbase + (cc % 3) * F_STAGE_B + bdoff;
        const __half* Bc = Bb + cc * 64;
#pragma unroll
        for (int u = 0; u < 4; u++)
            cp16(st + u * 32 * SROW * 2, Bc + (size_t)(u * 32) * K);
    };

    ldgA(0); cpaB(0); CP_COMMIT;
    stsA(0); CP_WAIT(0);
    __syncthreads();

    for (int cc = 0; cc < NC; cc++) {
        if (cc + 1 < NC) { ldgA(cc + 1); cpaB(cc + 1); CP_COMMIT; }

        uint32_t so = sbase + (cc % 3) * F_STAGE_B;
#pragma unroll
        for (int ks = 0; ks < 4; ks++) {
            uint32_t ah[4][4];
#pragma unroll
            for (int mt = 0; mt < 4; mt++) {
                uint32_t aoff = so + ((wm * 64 + mt * 16 + arow) * SROW + ks * 16 + akblk * 8) * 2;
                ldsm4(ah[mt][0], ah[mt][1], ah[mt][2], ah[mt][3], aoff);
            }
            uint32_t bh[2][4];
#pragma unroll
            for (int p = 0; p < 2; p++) {
                int nt = p * 2 + bntoff;
                uint32_t boff = so + (F_B_OFF_H + (wn * 32 + nt * 8 + bn) * SROW + ks * 16 + bkblk * 8) * 2;
                ldsm4(bh[p][0], bh[p][1], bh[p][2], bh[p][3], boff);
            }
#pragma unroll
            for (int mt = 0; mt < 4; mt++)
#pragma unroll
                for (int p = 0; p < 2; p++)
#pragma unroll
                    for (int h = 0; h < 2; h++)
                        mma16816(c[mt][p * 2 + h], ah[mt], &bh[p][h * 2]);
        }

        if (cc + 1 < NC) { stsA(cc + 1); CP_WAIT(0); }
        __syncthreads();
    }

    // epilogue: rows [wm*64,+64), cols [wn*32,+32), no bias
#pragma unroll
    for (int mt = 0; mt < 4; mt++) {
        int row = row0 + wm * 64 + mt * 16 + (lane >> 2);
#pragma unroll
        for (int n8 = 0; n8 < 4; n8++) {
            int col = col0 + wn * 32 + n8 * 8 + (lane & 3) * 2;
            __half2 o0 = __floats2half2_rn(c[mt][n8][0], c[mt][n8][1]);
            __half2 o1 = __floats2half2_rn(c[mt][n8][2], c[mt][n8][3]);
            *(__half2*)(C + (size_t)row * N + col)       = o0;
            *(__half2*)(C + (size_t)(row + 8) * N + col) = o1;
        }
    }
}

// ---------------- lead-mix ----------------
template <bool RELU>
__global__ __launch_bounds__(256) void k_mix(
    const __half* __restrict__ T, const float* __restrict__ bias,
    __half* __restrict__ out)
{
    int b  = blockIdx.x * 2 + (threadIdx.x >> 7);
    int f2 = threadIdx.x & 127;
    const __half2* Tb = (const __half2*)(T + (size_t)b * LEADS * HID) + f2;
    float2 t[LEADS];
#pragma unroll
    for (int j = 0; j < LEADS; j++) t[j] = __half22float2(Tb[j * 128]);
    float b0 = bias[f2 * 2], b1 = bias[f2 * 2 + 1];
    __half2* Ob = (__half2*)(out + (size_t)b * LEADS * HID) + f2;
#pragma unroll
    for (int i = 0; i < LEADS; i++) {
        float ax = b0, ay = b1;
#pragma unroll
        for (int j = 0; j < LEADS; j++) {
            float w = g_A[i * 12 + j];
            ax += w * t[j].x; ay += w * t[j].y;
        }
        if (RELU) { ax = fmaxf(ax, 0.0f); ay = fmaxf(ay, 0.0f); }
        Ob[i * 128] = __floats2half2_rn(ax, ay);
    }
}

// ---------------- attention via mma ----------------
#define SA 72
#define PA 24

__global__ __launch_bounds__(128) void k_attn(const __half* __restrict__ qkv,
                                              __half* __restrict__ o)
{
    __shared__ __align__(16) __half sQ[4][16 * SA];
    __shared__ __align__(16) __half sK[4][16 * SA];
    __shared__ __align__(16) __half sV[4][16 * SA];
    __shared__ __align__(16) __half sP[4][16 * PA];
    __shared__ float ss[4][12][12];

    int b    = blockIdx.x;
    int w    = threadIdx.x >> 5;
    int lane = threadIdx.x & 31;
    const __half* base = qkv + (size_t)b * LEADS * E3;

    uint4 z = make_uint4(0, 0, 0, 0);
    for (int i = lane; i < 36; i += 32) {
        ((uint4*)(sQ[w] + 12 * SA))[i] = z;
        ((uint4*)(sK[w] + 12 * SA))[i] = z;
        ((uint4*)(sV[w] + 12 * SA))[i] = z;
    }
    for (int i = lane; i < 48; i += 32)
        ((uint4*)sP[w])[i] = z;

#pragma unroll
    for (int i = 0; i < 3; i++) {
        int u = lane + 32 * i;
        int s = u >> 3, ch = (u & 7) * 8;
        *(uint4*)(sQ[w] + s * SA + ch) = *(const uint4*)(base + s * E3 +       w * 64 + ch);
        *(uint4*)(sK[w] + s * SA + ch) = *(const uint4*)(base + s * E3 + 256 + w * 64 + ch);
        *(uint4*)(sV[w] + s * SA + ch) = *(const uint4*)(base + s * E3 + 512 + w * 64 + ch);
    }
    __syncwarp();

    const int arow  = (lane & 7) | (((lane >> 3) & 1) << 3);
    const int akblk = (lane >> 4) & 1;
    const int brow  = (lane & 7) + ((lane >> 4) & 1) * 8;
    const int bkblk = (lane >> 3) & 1;
    const int r     = lane >> 2;
    const int cb    = (lane & 3) * 2;

    float cs[2][4] = {};
#pragma unroll
    for (int kc = 0; kc < 4; kc++) {
        uint32_t qa[4], kb[4];
        ldsm4(qa[0], qa[1], qa[2], qa[3],
              smem_u32(sQ[w] + arow * SA + kc * 16 + akblk * 8));
        ldsm4(kb[0], kb[1], kb[2], kb[3],
              smem_u32(sK[w] + brow * SA + kc * 16 + bkblk * 8));
        mma16816(cs[0], qa, &kb[0]);
        mma16816(cs[1], qa, &kb[2]);
    }
#pragma unroll
    for (int nt = 0; nt < 2; nt++) {
        int col = nt * 8 + cb;
        if (col < 12) {
            if (r < 12) {
                ss[w][r][col]     = cs[nt][0] * 0.125f;
                ss[w][r][col + 1] = cs[nt][1] * 0.125f;
            }
            if (r + 8 < 12) {
                ss[w][r + 8][col]     = cs[nt][2] * 0.125f;
                ss[w][r + 8][col + 1] = cs[nt][3] * 0.125f;
            }
        }
    }
    __syncwarp();

    if (lane < 12) {
        float mx = -1e30f;
        for (int t = 0; t < 12; t++) mx = fmaxf(mx, ss[w][lane][t]);
        float e[12], sum = 0.0f;
        for (int t = 0; t < 12; t++) { e[t] = expf(ss[w][lane][t] - mx); sum += e[t]; }
        float inv = 1.0f / sum;
        for (int t = 0; t < 12; t++) sP[w][lane * PA + t] = __float2half_rn(e[t] * inv);
    }
    __syncwarp();

    uint32_t pa[4];
    ldsm4(pa[0], pa[1], pa[2], pa[3], smem_u32(sP[w] + arow * PA + akblk * 8));
    float co[8][4] = {};
#pragma unroll
    for (int g4 = 0; g4 < 4; g4++) {
        uint32_t vb[4];
        ldsm4t(vb[0], vb[1], vb[2], vb[3],
               smem_u32(sV[w] + arow * SA + (lane >> 4) * 8 + g4 * 16));
        mma16816(co[g4 * 2],     pa, &vb[0]);
        mma16816(co[g4 * 2 + 1], pa, &vb[2]);
    }

    __half* ob = o + ((size_t)b * LEADS) * HID + w * 64;
#pragma unroll
    for (int nt = 0; nt < 8; nt++) {
        int d = nt * 8 + cb;
        if (r < 12)
            *(__half2*)(ob + (size_t)r * HID + d) = __floats2half2_rn(co[nt][0], co[nt][1]);
        if (r + 8 < 12)
            *(__half2*)(ob + (size_t)(r + 8) * HID + d) = __floats2half2_rn(co[nt][2], co[nt][3]);
    }
}

// ---------------- residual + LayerNorm ----------------
__global__ __launch_bounds__(256) void k_ln(
    const __half* __restrict__ h, const __half* __restrict__ a,
    const float* __restrict__ g, const float* __restrict__ bta,
    __half* __restrict__ out)
{
    int row  = blockIdx.x * 8 + (threadIdx.x >> 5);
    int lane = threadIdx.x & 31;
    const __half2* hp = (const __half2*)(h + (size_t)row * HID);
    const __half2* ap = (const __half2*)(a + (size_t)row * HID);

    float v[8];
    float sum = 0.0f;
#pragma unroll
    for (int j = 0; j < 4; j++) {
        int c2 = lane + 32 * j;
        float2 hv = __half22float2(hp[c2]);
        float2 av = __half22float2(ap[c2]);
        v[2 * j]     = hv.x + av.x;
        v[2 * j + 1] = hv.y + av.y;
        sum += v[2 * j] + v[2 * j + 1];
    }
#pragma unroll
    for (int off = 16; off; off >>= 1) sum += __shfl_xor_sync(0xFFFFFFFFu, sum, off);
    float mu = sum * (1.0f / 256.0f);

    float vs = 0.0f;
#pragma unroll
    for (int j = 0; j < 8; j++) { float d = v[j] - mu; vs += d * d; }
#pragma unroll
    for (int off = 16; off; off >>= 1) vs += __shfl_xor_sync(0xFFFFFFFFu, vs, off);
    float rs = rsqrtf(vs * (1.0f / 256.0f) + 1e-5f);

    __half2* op = (__half2*)(out + (size_t)row * HID);
#pragma unroll
    for (int j = 0; j < 4; j++) {
        int c2 = lane + 32 * j;
        float o0 = (v[2 * j]     - mu) * rs * g[c2 * 2]     + bta[c2 * 2];
        float o1 = (v[2 * j + 1] - mu) * rs * g[c2 * 2 + 1] + bta[c2 * 2 + 1];
        op[c2] = __floats2half2_rn(o0, o1);
    }
}

// ---------------- final: gcn3 mix + pooling ----------------
__global__ __launch_bounds__(256) void k_final(
    const __half* __restrict__ T3, const float* __restrict__ b3,
    float* __restrict__ out)
{
    __shared__ float red[12][8];
    __shared__ float sw[12];
    int b = blockIdx.x, f = threadIdx.x;
    int lane = f & 31, wid = f >> 5;

    float t[LEADS];
#pragma unroll
    for (int j = 0; j < LEADS; j++)
        t[j] = __half2float(T3[((size_t)b * LEADS + j) * HID + f]);

    float bias = b3[f];
    float h3[LEADS];
#pragma unroll
    for (int i = 0; i < LEADS; i++) {
        float acc = bias;
#pragma unroll
        for (int j = 0; j < LEADS; j++) acc += g_A[i * 12 + j] * t[j];
        h3[i] = acc;
    }

#pragma unroll
    for (int i = 0; i < LEADS; i++) {
        float s = h3[i];
#pragma unroll
        for (int off = 16; off; off >>= 1) s += __shfl_xor_sync(0xFFFFFFFFu, s, off);
        if (lane == 0) red[i][wid] = s;
    }
    __syncthreads();
    if (f < 12) {
        float s = 0.0f;
        for (int w = 0; w < 8; w++) s += red[f][w];
        sw[f] = s * (1.0f / 256.0f);
    }
    __syncthreads();
    if (f == 0) {
        float mx = -1e30f;
        for (int i = 0; i < 12; i++) mx = fmaxf(mx, sw[i]);
        float e[12], sum = 0.0f;
        for (int i = 0; i < 12; i++) { e[i] = expf(sw[i] - mx); sum += e[i]; }
        float inv = 1.0f / sum;
        for (int i = 0; i < 12; i++) sw[i] = e[i] * inv;
    }
    __syncthreads();

    float ws = 0.0f, mx = -1e30f;
#pragma unroll
    for (int i = 0; i < LEADS; i++) {
        ws += h3[i] * sw[i];
        mx = fmaxf(mx, h3[i]);
    }
    out[(size_t)b * 512 + f]       = ws;
    out[(size_t)b * 512 + 256 + f] = mx;
}

// ---------------- launcher ----------------
extern "C" void kernel_launch(void* const* d_in, const int* in_sizes, int n_in,
                              void* d_out, int out_size)
{
    const float* x    = (const float*)d_in[0];
    const float* W1   = (const float*)d_in[1];
    const float* b1   = (const float*)d_in[2];
    const float* W2   = (const float*)d_in[3];
    const float* b2   = (const float*)d_in[4];
    const float* W3   = (const float*)d_in[5];
    const float* b3   = (const float*)d_in[6];
    const float* inW  = (const float*)d_in[7];
    const float* inB  = (const float*)d_in[8];
    const float* outW = (const float*)d_in[9];
    const float* outB = (const float*)d_in[10];
    const float* lng  = (const float*)d_in[11];
    const float* lnb  = (const float*)d_in[12];
    float* out = (float*)d_out;

    __half *bufQ, *buf1, *buf2, *buf3;
    cudaGetSymbolAddress((void**)&bufQ, g_qkv);
    cudaGetSymbolAddress((void**)&buf1, g_buf1);
    cudaGetSymbolAddress((void**)&buf2, g_buf2);
    cudaGetSymbolAddress((void**)&buf3, g_buf3);

    __half *w1, *w2, *w3, *iw, *ow;
    cudaGetSymbolAddress((void**)&w1, g_W1);
    cudaGetSymbolAddress((void**)&w2, g_W2);
    cudaGetSymbolAddress((void**)&w3, g_W3);
    cudaGetSymbolAddress((void**)&iw, g_Iw);
    cudaGetSymbolAddress((void**)&ow, g_Ow);

    cudaFuncSetAttribute(k_hgemm<false>, cudaFuncAttributeMaxDynamicSharedMemorySize, SMEM_BYTES);
    cudaFuncSetAttribute(k_hgemm<true>,  cudaFuncAttributeMaxDynamicSharedMemorySize, SMEM_BYTES);
    cudaFuncSetAttribute(k_hgemm_f32a,   cudaFuncAttributeMaxDynamicSharedMemorySize, F_SMEM_BYTES);

    // 1: prep (weights only)
    k_prep<<<PREP_BLOCKS, 256>>>(W1, W2, W3, inW, outW);

    dim3 gH(2, MROWS / 256);   // N=256 (fp16 GEMMs)
    dim3 gQ(6, MROWS / 256);   // N=768
    dim3 gF(2, MROWS / 128);   // f32a gcn1 (128-row tiles)

    // 2: gcn1 GEMM directly on fp32 x; 3: mix
    k_hgemm_f32a<<<gF, 256, F_SMEM_BYTES>>>(x, w1, buf1, FIN, HID);
    k_mix<true><<<B_SZ / 2, 256>>>(buf1, b1, buf2);

    // 4: gcn2 GEMM; 5: mix
    k_hgemm<false><<<gH, 256, SMEM_BYTES>>>(buf2, w2, nullptr, buf1, HID, HID);
    k_mix<true><<<B_SZ / 2, 256>>>(buf1, b2, buf3);     // buf3 = h2 (residual)

    // 6: qkv GEMM
    k_hgemm<true><<<gQ, 256, SMEM_BYTES>>>(buf3, iw, inB, bufQ, HID, E3);

    // 7: attention
    k_attn<<<B_SZ, 128>>>(bufQ, buf1);

    // 8: out_proj GEMM
    k_hgemm<true><<<gH, 256, SMEM_BYTES>>>(buf1, ow, outB, buf2, HID, HID);

    // 9: residual + LN
    k_ln<<<MROWS / 8, 256>>>(buf3, buf2, lng, lnb, buf1);

    // 10: gcn3 GEMM
    k_hgemm<false><<<gH, 256, SMEM_BYTES>>>(buf1, w3, nullptr, buf2, HID, HID);

    // 11: pooling
    k_final<<<B_SZ, 256>>>(buf2, b3, out);
}

// round 15
// speedup vs baseline: 1.2970x; 1.2970x over previous
#include <cuda_runtime.h>
#include <cuda_fp16.h>
#include <cstdint>
#include <math.h>

#define B_SZ   8192
#define LEADS  12
#define FIN    512
#define HID    256
#define E3     768
#define MROWS  (B_SZ * LEADS)   // 98304

// ---------------- static scratch ----------------
__device__ float g_A[LEADS * LEADS];
__device__ __half g_qkv[(size_t)MROWS * E3];   // also reused as x16 before qkv
__device__ __half g_buf1[(size_t)MROWS * HID];
__device__ __half g_buf2[(size_t)MROWS * HID];
__device__ __half g_buf3[(size_t)MROWS * HID];

__device__ __half g_W1[HID * FIN];
__device__ __half g_W2[HID * HID];
__device__ __half g_W3[HID * HID];
__device__ __half g_Iw[E3 * HID];
__device__ __half g_Ow[HID * HID];

// ---------------- helpers ----------------
__device__ __forceinline__ uint32_t smem_u32(const void* p) {
    uint32_t a;
    asm("{ .reg .u64 t; cvta.to.shared.u64 t, %1; cvt.u32.u64 %0, t; }" : "=r"(a) : "l"(p));
    return a;
}
__device__ __forceinline__ void ldsm4(uint32_t& r0, uint32_t& r1, uint32_t& r2, uint32_t& r3,
                                      uint32_t a) {
    asm volatile("ldmatrix.sync.aligned.m8n8.x4.shared.b16 {%0,%1,%2,%3}, [%4];"
                 : "=r"(r0), "=r"(r1), "=r"(r2), "=r"(r3) : "r"(a));
}
__device__ __forceinline__ void ldsm4t(uint32_t& r0, uint32_t& r1, uint32_t& r2, uint32_t& r3,
                                       uint32_t a) {
    asm volatile("ldmatrix.sync.aligned.m8n8.x4.trans.shared.b16 {%0,%1,%2,%3}, [%4];"
                 : "=r"(r0), "=r"(r1), "=r"(r2), "=r"(r3) : "r"(a));
}
__device__ __forceinline__ void mma16816(float* c, const uint32_t* a, const uint32_t* b) {
    asm volatile("mma.sync.aligned.m16n8k16.row.col.f32.f16.f16.f32 "
                 "{%0,%1,%2,%3}, {%4,%5,%6,%7}, {%8,%9}, {%0,%1,%2,%3};"
                 : "+f"(c[0]), "+f"(c[1]), "+f"(c[2]), "+f"(c[3])
                 : "r"(a[0]), "r"(a[1]), "r"(a[2]), "r"(a[3]), "r"(b[0]), "r"(b[1]));
}
__device__ __forceinline__ void cp16(uint32_t d, const void* g) {
    asm volatile("cp.async.ca.shared.global [%0], [%1], 16;" :: "r"(d), "l"(g));
}
#define CP_COMMIT  asm volatile("cp.async.commit_group;" ::: "memory")
#define CP_WAIT(n) asm volatile("cp.async.wait_group %0;" :: "n"(n) : "memory")

// ---------------- fused prep (R12): A_norm + weights + x->fp16 ----------------
#define PREP_X4   12582912
#define PREP_W1   (PREP_X4 + 131072)
#define PREP_W2   (PREP_W1 + 65536)
#define PREP_W3   (PREP_W2 + 65536)
#define PREP_IW   (PREP_W3 + 196608)
#define PREP_OW   (PREP_IW + 65536)
#define PREP_BLOCKS  (PREP_OW / 256)

__global__ void k_prep(const float* __restrict__ x,  const float* __restrict__ W1,
                       const float* __restrict__ W2, const float* __restrict__ W3,
                       const float* __restrict__ inW, const float* __restrict__ outW,
                       __half* __restrict__ x16)
{
    size_t gid = (size_t)blockIdx.x * blockDim.x + threadIdx.x;
    if (gid == 0) {
        const int ci[18] = {0,0,1,0,1,2,0,1,1,2,6,7,8,9,10,0,1,2};
        const int cj[18] = {1,2,2,3,3,3,4,4,5,5,7,8,9,10,11,6,9,11};
        float A[12][12];
        for (int i = 0; i < 12; i++)
            for (int j = 0; j < 12; j++) A[i][j] = (i == j) ? 1.0f : 0.0f;
        for (int e = 0; e < 18; e++) { A[ci[e]][cj[e]] = 1.0f; A[cj[e]][ci[e]] = 1.0f; }
        float dinv[12];
        for (int i = 0; i < 12; i++) {
            float s = 0.0f;
            for (int j = 0; j < 12; j++) s += A[i][j];
            dinv[i] = 1.0f / sqrtf(s);
        }
        for (int i = 0; i < 12; i++)
            for (int j = 0; j < 12; j++) g_A[i * 12 + j] = dinv[i] * A[i][j] * dinv[j];
    }
    if (gid < PREP_X4) {
        float4 v = ((const float4*)x)[gid];
        ((__half2*)x16)[gid * 2]     = __floats2half2_rn(v.x, v.y);
        ((__half2*)x16)[gid * 2 + 1] = __floats2half2_rn(v.z, v.w);
        return;
    }
    if (gid < PREP_W1) {
        size_t l = gid - PREP_X4;
        int k = (int)(l >> 8), n = (int)(l & 255);
        g_W1[n * FIN + k] = __float2half_rn(W1[l]);
        return;
    }
    if (gid < PREP_W2) {
        size_t l = gid - PREP_W1;
        int k = (int)(l >> 8), n = (int)(l & 255);
        g_W2[n * HID + k] = __float2half_rn(W2[l]);
        return;
    }
    if (gid < PREP_W3) {
        size_t l = gid - PREP_W2;
        int k = (int)(l >> 8), n = (int)(l & 255);
        g_W3[n * HID + k] = __float2half_rn(W3[l]);
        return;
    }
    if (gid < PREP_IW) {
        size_t l = gid - PREP_W3;
        g_Iw[l] = __float2half_rn(inW[l]);
        return;
    }
    if (gid < PREP_OW) {
        size_t l = gid - PREP_IW;
        g_Ow[l] = __float2half_rn(outW[l]);
        return;
    }
}

// ---------------- fp16 GEMM core (R12, unchanged) ----------------
// Block tile 256x128, 256 threads (8 warps 4Mx2N), warp tile 64x64, BK=64.
#define SROW    72
#define B_OFF_H (256 * SROW)
#define STAGE_H (384 * SROW)
#define STAGE_B (STAGE_H * 2)
#define NSTAGE  3
#define SMEM_BYTES (NSTAGE * STAGE_B)

struct GemmCtx {
    int lane, wm, wn;
    int arow, akblk, bn, bkblk, bntoff;
};

__device__ __forceinline__ GemmCtx make_ctx(int tid) {
    GemmCtx g;
    g.lane = tid & 31;
    int w = tid >> 5;
    g.wm = w >> 1;
    g.wn = w & 1;
    g.arow  = (g.lane & 7) | (((g.lane >> 3) & 1) << 3);
    g.akblk = (g.lane >> 4) & 1;
    int bwhich = g.lane >> 3;
    g.bn     = g.lane & 7;
    g.bkblk  = bwhich & 1;
    g.bntoff = bwhich >> 1;
    return g;
}

__device__ __forceinline__ void load_frags(const GemmCtx& g, uint32_t so, int ks,
                                           uint32_t ah[4][4], uint32_t bh[4][4]) {
#pragma unroll
    for (int mt = 0; mt < 4; mt++) {
        uint32_t aoff = so + ((g.wm * 64 + mt * 16 + g.arow) * SROW + ks * 16 + g.akblk * 8) * 2;
        ldsm4(ah[mt][0], ah[mt][1], ah[mt][2], ah[mt][3], aoff);
    }
#pragma unroll
    for (int p = 0; p < 4; p++) {
        int nt = p * 2 + g.bntoff;
        uint32_t boff = so + (B_OFF_H + (g.wn * 64 + nt * 8 + g.bn) * SROW + ks * 16 + g.bkblk * 8) * 2;
        ldsm4(bh[p][0], bh[p][1], bh[p][2], bh[p][3], boff);
    }
}

__device__ __forceinline__ void do_mmas(const uint32_t ah[4][4], const uint32_t bh[4][4],
                                        float c[4][8][4]) {
#pragma unroll
    for (int mt = 0; mt < 4; mt++)
#pragma unroll
        for (int p = 0; p < 4; p++)
#pragma unroll
            for (int h = 0; h < 2; h++)
                mma16816(c[mt][p * 2 + h], ah[mt], &bh[p][h * 2]);
}

template <bool BIAS>
__global__ __launch_bounds__(256, 1) void k_hgemm(
    const __half* __restrict__ A,
    const __half* __restrict__ B,
    const float* __restrict__ bias,
    __half* __restrict__ C,
    int K, int N)
{
    extern __shared__ __half sm[];
    const int tid  = threadIdx.x;
    const int row0 = blockIdx.y * 256;
    const int col0 = blockIdx.x * 128;
    const int NC   = K >> 6;
    const uint32_t sbase = smem_u32(sm);
    GemmCtx g = make_ctx(tid);

    float c[4][8][4];
#pragma unroll
    for (int i = 0; i < 4; i++)
#pragma unroll
        for (int j = 0; j < 8; j++)
#pragma unroll
            for (int q = 0; q < 4; q++) c[i][j][q] = 0.0f;

    const int rr = tid >> 3;
    const int qq = (tid & 7) * 8;
    const __half* Ab = A + (size_t)(row0 + rr) * K + qq;
    const __half* Bb = B + (size_t)(col0 + rr) * K + qq;
    const uint32_t doff = (rr * SROW + qq) * 2;

    auto cpa = [&](int cc) {
        uint32_t st = sbase + (cc % 3) * STAGE_B + doff;
        const __half* Ac = Ab + cc * 64;
        const __half* Bc = Bb + cc * 64;
#pragma unroll
        for (int u = 0; u < 8; u++)
            cp16(st + u * 32 * SROW * 2, Ac + (size_t)(u * 32) * K);
#pragma unroll
        for (int u = 0; u < 4; u++)
            cp16(st + (B_OFF_H + u * 32 * SROW) * 2, Bc + (size_t)(u * 32) * K);
    };

    int npre = NC < 2 ? NC : 2;
    for (int s = 0; s < npre; s++) { cpa(s); CP_COMMIT; }

    uint32_t ah[2][4][4], bh[2][4][4];

    for (int cc = 0; cc < NC; cc++) {
        if (cc + 1 < NC) CP_WAIT(1); else CP_WAIT(0);
        __syncthreads();
        if (cc + 2 < NC) { cpa(cc + 2); CP_COMMIT; }

        uint32_t so = sbase + (cc % 3) * STAGE_B;
        load_frags(g, so, 0, ah[0], bh[0]);
#pragma unroll
        for (int ks = 0; ks < 4; ks++) {
            int cur = ks & 1;
            if (ks < 3) load_frags(g, so, ks + 1, ah[cur ^ 1], bh[cur ^ 1]);
            do_mmas(ah[cur], bh[cur], c);
        }
        __syncthreads();
    }

#pragma unroll
    for (int mt = 0; mt < 4; mt++) {
        int row = row0 + g.wm * 64 + mt * 16 + (g.lane >> 2);
#pragma unroll
        for (int n8 = 0; n8 < 8; n8++) {
            int col = col0 + g.wn * 64 + n8 * 8 + (g.lane & 3) * 2;
            float b0 = 0.0f, b1 = 0.0f;
            if (BIAS) { b0 = bias[col]; b1 = bias[col + 1]; }
            __half2 o0 = __floats2half2_rn(c[mt][n8][0] + b0, c[mt][n8][1] + b1);
            __half2 o1 = __floats2half2_rn(c[mt][n8][2] + b0, c[mt][n8][3] + b1);
            *(__half2*)(C + (size_t)row * N + col)       = o0;
            *(__half2*)(C + (size_t)(row + 8) * N + col) = o1;
        }
    }
}

// ---------------- fused GEMM + lead-mix + bias + ReLU ----------------
// Block tile 192x128 (16 batches), 256 threads (8 warps 4Mx2N), warp tile 48x64.
// Output N must be 256 (grid.x = 2 col tiles of 128).
#define MB_OFF_H (192 * SROW)
#define M_STAGE_H (320 * SROW)
#define M_STAGE_B (M_STAGE_H * 2)
#define M_SMEM (NSTAGE * M_STAGE_B)   // 138240
#define CST 132

__global__ __launch_bounds__(256, 1) void k_hgemm_mix(
    const __half* __restrict__ A,
    const __half* __restrict__ B,
    const float* __restrict__ bias,
    __half* __restrict__ C,
    int K)
{
    extern __shared__ __half sm[];
    __shared__ float sA12[144];
    const int tid  = threadIdx.x;
    const int lane = tid & 31;
    const int w    = tid >> 5;
    const int wm   = w >> 1;        // 0..3, 48 rows each
    const int wn   = w & 1;         // 0..1, 64 cols each
    const int row0 = blockIdx.y * 192;
    const int col0 = blockIdx.x * 128;
    const int NC   = K >> 6;
    const uint32_t sbase = smem_u32(sm);

    if (tid < 144) sA12[tid] = g_A[tid];

    const int arow  = (lane & 7) | (((lane >> 3) & 1) << 3);
    const int akblk = (lane >> 4) & 1;
    const int bwhich = lane >> 3;
    const int bn     = lane & 7;
    const int bkblk  = bwhich & 1;
    const int bntoff = bwhich >> 1;

    float c[3][8][4];
#pragma unroll
    for (int i = 0; i < 3; i++)
#pragma unroll
        for (int j = 0; j < 8; j++)
#pragma unroll
            for (int q = 0; q < 4; q++) c[i][j][q] = 0.0f;

    // cp.async: 1536 A units (192 rows x 8) + 1024 B units (128 rows x 8) = 2560 = 10/thread
    auto cpa = [&](int cc) {
        uint32_t stb = sbase + (cc % 3) * M_STAGE_B;
#pragma unroll
        for (int i = 0; i < 6; i++) {              // A units: u = tid + i*256 < 1536
            int u = tid + i * 256;
            int r = u >> 3, q = (u & 7) * 8;
            cp16(stb + (r * SROW + q) * 2, A + (size_t)(row0 + r) * K + cc * 64 + q);
        }
#pragma unroll
        for (int i = 0; i < 4; i++) {              // B units
            int v = tid + i * 256;
            int r = v >> 3, q = (v & 7) * 8;
            cp16(stb + (MB_OFF_H + r * SROW + q) * 2, B + (size_t)(col0 + r) * K + cc * 64 + q);
        }
    };

    auto lfr = [&](uint32_t so, int ks, uint32_t ah[3][4], uint32_t bh[4][4]) {
#pragma unroll
        for (int mt = 0; mt < 3; mt++) {
            uint32_t aoff = so + ((wm * 48 + mt * 16 + arow) * SROW + ks * 16 + akblk * 8) * 2;
            ldsm4(ah[mt][0], ah[mt][1], ah[mt][2], ah[mt][3], aoff);
        }
#pragma unroll
        for (int p = 0; p < 4; p++) {
            int nt = p * 2 + bntoff;
            uint32_t boff = so + (MB_OFF_H + (wn * 64 + nt * 8 + bn) * SROW + ks * 16 + bkblk * 8) * 2;
            ldsm4(bh[p][0], bh[p][1], bh[p][2], bh[p][3], boff);
        }
    };

    int npre = NC < 2 ? NC : 2;
    for (int s = 0; s < npre; s++) { cpa(s); CP_COMMIT; }

    uint32_t ah[2][3][4], bh[2][4][4];

    for (int cc = 0; cc < NC; cc++) {
        if (cc + 1 < NC) CP_WAIT(1); else CP_WAIT(0);
        __syncthreads();
        if (cc + 2 < NC) { cpa(cc + 2); CP_COMMIT; }

        uint32_t so = sbase + (cc % 3) * M_STAGE_B;
        lfr(so, 0, ah[0], bh[0]);
#pragma unroll
        for (int ks = 0; ks < 4; ks++) {
            int cur = ks & 1;
            if (ks < 3) lfr(so, ks + 1, ah[cur ^ 1], bh[cur ^ 1]);
#pragma unroll
            for (int mt = 0; mt < 3; mt++)
#pragma unroll
                for (int p = 0; p < 4; p++)
#pragma unroll
                    for (int h = 0; h < 2; h++)
                        mma16816(c[mt][p * 2 + h], ah[cur][mt], &bh[cur][p][h * 2]);
        }
        __syncthreads();
    }

    // stage fp32 C into smem (reuse stage buffers; all reads done after last sync)
    float* Cst = (float*)sm;
#pragma unroll
    for (int mt = 0; mt < 3; mt++) {
        int r = wm * 48 + mt * 16 + (lane >> 2);
#pragma unroll
        for (int n8 = 0; n8 < 8; n8++) {
            int cl = wn * 64 + n8 * 8 + (lane & 3) * 2;
            *(float2*)&Cst[r * CST + cl]       = make_float2(c[mt][n8][0], c[mt][n8][1]);
            *(float2*)&Cst[(r + 8) * CST + cl] = make_float2(c[mt][n8][2], c[mt][n8][3]);
        }
    }
    __syncthreads();

    // lead-mix + bias + relu, write fp16
    const int bg0 = blockIdx.y * 16;
#pragma unroll
    for (int it = 0; it < 4; it++) {
        int u = tid + it * 256;                    // 0..1023
        int b = u >> 6, f2 = u & 63;
        int f = f2 * 2;
        float t0[12], t1[12];
#pragma unroll
        for (int j = 0; j < 12; j++) {
            float2 v = *(float2*)&Cst[(b * 12 + j) * CST + f];
            t0[j] = v.x; t1[j] = v.y;
        }
        float bb0 = bias[col0 + f], bb1 = bias[col0 + f + 1];
        __half* ob = C + ((size_t)(bg0 + b) * 12) * HID + col0 + f;
#pragma unroll
        for (int i = 0; i < 12; i++) {
            float ax = bb0, ay = bb1;
#pragma unroll
            for (int j = 0; j < 12; j++) {
                float wv = sA12[i * 12 + j];
                ax += wv * t0[j]; ay += wv * t1[j];
            }
            ax = fmaxf(ax, 0.0f); ay = fmaxf(ay, 0.0f);
            *(__half2*)(ob + (size_t)i * HID) = __floats2half2_rn(ax, ay);
        }
    }
}

// ---------------- attention via mma ----------------
#define SA 72
#define PA 24

__global__ __launch_bounds__(128) void k_attn(const __half* __restrict__ qkv,
                                              __half* __restrict__ o)
{
    __shared__ __align__(16) __half sQ[4][16 * SA];
    __shared__ __align__(16) __half sK[4][16 * SA];
    __shared__ __align__(16) __half sV[4][16 * SA];
    __shared__ __align__(16) __half sP[4][16 * PA];
    __shared__ float ss[4][12][12];

    int b    = blockIdx.x;
    int w    = threadIdx.x >> 5;
    int lane = threadIdx.x & 31;
    const __half* base = qkv + (size_t)b * LEADS * E3;

    uint4 z = make_uint4(0, 0, 0, 0);
    for (int i = lane; i < 36; i += 32) {
        ((uint4*)(sQ[w] + 12 * SA))[i] = z;
        ((uint4*)(sK[w] + 12 * SA))[i] = z;
        ((uint4*)(sV[w] + 12 * SA))[i] = z;
    }
    for (int i = lane; i < 48; i += 32)
        ((uint4*)sP[w])[i] = z;

#pragma unroll
    for (int i = 0; i < 3; i++) {
        int u = lane + 32 * i;
        int s = u >> 3, ch = (u & 7) * 8;
        *(uint4*)(sQ[w] + s * SA + ch) = *(const uint4*)(base + s * E3 +       w * 64 + ch);
        *(uint4*)(sK[w] + s * SA + ch) = *(const uint4*)(base + s * E3 + 256 + w * 64 + ch);
        *(uint4*)(sV[w] + s * SA + ch) = *(const uint4*)(base + s * E3 + 512 + w * 64 + ch);
    }
    __syncwarp();

    const int arow  = (lane & 7) | (((lane >> 3) & 1) << 3);
    const int akblk = (lane >> 4) & 1;
    const int brow  = (lane & 7) + ((lane >> 4) & 1) * 8;
    const int bkblk = (lane >> 3) & 1;
    const int r     = lane >> 2;
    const int cb    = (lane & 3) * 2;

    float cs[2][4] = {};
#pragma unroll
    for (int kc = 0; kc < 4; kc++) {
        uint32_t qa[4], kb[4];
        ldsm4(qa[0], qa[1], qa[2], qa[3],
              smem_u32(sQ[w] + arow * SA + kc * 16 + akblk * 8));
        ldsm4(kb[0], kb[1], kb[2], kb[3],
              smem_u32(sK[w] + brow * SA + kc * 16 + bkblk * 8));
        mma16816(cs[0], qa, &kb[0]);
        mma16816(cs[1], qa, &kb[2]);
    }
#pragma unroll
    for (int nt = 0; nt < 2; nt++) {
        int col = nt * 8 + cb;
        if (col < 12) {
            if (r < 12) {
                ss[w][r][col]     = cs[nt][0] * 0.125f;
                ss[w][r][col + 1] = cs[nt][1] * 0.125f;
            }
            if (r + 8 < 12) {
                ss[w][r + 8][col]     = cs[nt][2] * 0.125f;
                ss[w][r + 8][col + 1] = cs[nt][3] * 0.125f;
            }
        }
    }
    __syncwarp();

    if (lane < 12) {
        float mx = -1e30f;
        for (int t = 0; t < 12; t++) mx = fmaxf(mx, ss[w][lane][t]);
        float e[12], sum = 0.0f;
        for (int t = 0; t < 12; t++) { e[t] = expf(ss[w][lane][t] - mx); sum += e[t]; }
        float inv = 1.0f / sum;
        for (int t = 0; t < 12; t++) sP[w][lane * PA + t] = __float2half_rn(e[t] * inv);
    }
    __syncwarp();

    uint32_t pa[4];
    ldsm4(pa[0], pa[1], pa[2], pa[3], smem_u32(sP[w] + arow * PA + akblk * 8));
    float co[8][4] = {};
#pragma unroll
    for (int g4 = 0; g4 < 4; g4++) {
        uint32_t vb[4];
        ldsm4t(vb[0], vb[1], vb[2], vb[3],
               smem_u32(sV[w] + arow * SA + (lane >> 4) * 8 + g4 * 16));
        mma16816(co[g4 * 2],     pa, &vb[0]);
        mma16816(co[g4 * 2 + 1], pa, &vb[2]);
    }

    __half* ob = o + ((size_t)b * LEADS) * HID + w * 64;
#pragma unroll
    for (int nt = 0; nt < 8; nt++) {
        int d = nt * 8 + cb;
        if (r < 12)
            *(__half2*)(ob + (size_t)r * HID + d) = __floats2half2_rn(co[nt][0], co[nt][1]);
        if (r + 8 < 12)
            *(__half2*)(ob + (size_t)(r + 8) * HID + d) = __floats2half2_rn(co[nt][2], co[nt][3]);
    }
}

// ---------------- residual + LayerNorm ----------------
__global__ __launch_bounds__(256) void k_ln(
    const __half* __restrict__ h, const __half* __restrict__ a,
    const float* __restrict__ g, const float* __restrict__ bta,
    __half* __restrict__ out)
{
    int row  = blockIdx.x * 8 + (threadIdx.x >> 5);
    int lane = threadIdx.x & 31;
    const __half2* hp = (const __half2*)(h + (size_t)row * HID);
    const __half2* ap = (const __half2*)(a + (size_t)row * HID);

    float v[8];
    float sum = 0.0f;
#pragma unroll
    for (int j = 0; j < 4; j++) {
        int c2 = lane + 32 * j;
        float2 hv = __half22float2(hp[c2]);
        float2 av = __half22float2(ap[c2]);
        v[2 * j]     = hv.x + av.x;
        v[2 * j + 1] = hv.y + av.y;
        sum += v[2 * j] + v[2 * j + 1];
    }
#pragma unroll
    for (int off = 16; off; off >>= 1) sum += __shfl_xor_sync(0xFFFFFFFFu, sum, off);
    float mu = sum * (1.0f / 256.0f);

    float vs = 0.0f;
#pragma unroll
    for (int j = 0; j < 8; j++) { float d = v[j] - mu; vs += d * d; }
#pragma unroll
    for (int off = 16; off; off >>= 1) vs += __shfl_xor_sync(0xFFFFFFFFu, vs, off);
    float rs = rsqrtf(vs * (1.0f / 256.0f) + 1e-5f);

    __half2* op = (__half2*)(out + (size_t)row * HID);
#pragma unroll
    for (int j = 0; j < 4; j++) {
        int c2 = lane + 32 * j;
        float o0 = (v[2 * j]     - mu) * rs * g[c2 * 2]     + bta[c2 * 2];
        float o1 = (v[2 * j + 1] - mu) * rs * g[c2 * 2 + 1] + bta[c2 * 2 + 1];
        op[c2] = __floats2half2_rn(o0, o1);
    }
}

// ---------------- final: gcn3 mix + pooling ----------------
__global__ __launch_bounds__(256) void k_final(
    const __half* __restrict__ T3, const float* __restrict__ b3,
    float* __restrict__ out)
{
    __shared__ float red[12][8];
    __shared__ float sw[12];
    int b = blockIdx.x, f = threadIdx.x;
    int lane = f & 31, wid = f >> 5;

    float t[LEADS];
#pragma unroll
    for (int j = 0; j < LEADS; j++)
        t[j] = __half2float(T3[((size_t)b * LEADS + j) * HID + f]);

    float bias = b3[f];
    float h3[LEADS];
#pragma unroll
    for (int i = 0; i < LEADS; i++) {
        float acc = bias;
#pragma unroll
        for (int j = 0; j < LEADS; j++) acc += g_A[i * 12 + j] * t[j];
        h3[i] = acc;
    }

#pragma unroll
    for (int i = 0; i < LEADS; i++) {
        float s = h3[i];
#pragma unroll
        for (int off = 16; off; off >>= 1) s += __shfl_xor_sync(0xFFFFFFFFu, s, off);
        if (lane == 0) red[i][wid] = s;
    }
    __syncthreads();
    if (f < 12) {
        float s = 0.0f;
        for (int w = 0; w < 8; w++) s += red[f][w];
        sw[f] = s * (1.0f / 256.0f);
    }
    __syncthreads();
    if (f == 0) {
        float mx = -1e30f;
        for (int i = 0; i < 12; i++) mx = fmaxf(mx, sw[i]);
        float e[12], sum = 0.0f;
        for (int i = 0; i < 12; i++) { e[i] = expf(sw[i] - mx); sum += e[i]; }
        float inv = 1.0f / sum;
        for (int i = 0; i < 12; i++) sw[i] = e[i] * inv;
    }
    __syncthreads();

    float ws = 0.0f, mx = -1e30f;
#pragma unroll
    for (int i = 0; i < LEADS; i++) {
        ws += h3[i] * sw[i];
        mx = fmaxf(mx, h3[i]);
    }
    out[(size_t)b * 512 + f]       = ws;
    out[(size_t)b * 512 + 256 + f] = mx;
}

// ---------------- launcher ----------------
extern "C" void kernel_launch(void* const* d_in, const int* in_sizes, int n_in,
                              void* d_out, int out_size)
{
    const float* x    = (const float*)d_in[0];
    const float* W1   = (const float*)d_in[1];
    const float* b1   = (const float*)d_in[2];
    const float* W2   = (const float*)d_in[3];
    const float* b2   = (const float*)d_in[4];
    const float* W3   = (const float*)d_in[5];
    const float* b3   = (const float*)d_in[6];
    const float* inW  = (const float*)d_in[7];
    const float* inB  = (const float*)d_in[8];
    const float* outW = (const float*)d_in[9];
    const float* outB = (const float*)d_in[10];
    const float* lng  = (const float*)d_in[11];
    const float* lnb  = (const float*)d_in[12];
    float* out = (float*)d_out;

    __half *bufQ, *buf1, *buf2, *buf3;
    cudaGetSymbolAddress((void**)&bufQ, g_qkv);
    cudaGetSymbolAddress((void**)&buf1, g_buf1);
    cudaGetSymbolAddress((void**)&buf2, g_buf2);
    cudaGetSymbolAddress((void**)&buf3, g_buf3);

    __half *w1, *w2, *w3, *iw, *ow;
    cudaGetSymbolAddress((void**)&w1, g_W1);
    cudaGetSymbolAddress((void**)&w2, g_W2);
    cudaGetSymbolAddress((void**)&w3, g_W3);
    cudaGetSymbolAddress((void**)&iw, g_Iw);
    cudaGetSymbolAddress((void**)&ow, g_Ow);

    cudaFuncSetAttribute(k_hgemm<false>, cudaFuncAttributeMaxDynamicSharedMemorySize, SMEM_BYTES);
    cudaFuncSetAttribute(k_hgemm<true>,  cudaFuncAttributeMaxDynamicSharedMemorySize, SMEM_BYTES);
    cudaFuncSetAttribute(k_hgemm_mix,    cudaFuncAttributeMaxDynamicSharedMemorySize, M_SMEM);

    __half* x16 = bufQ;

    // 1: fused prep
    k_prep<<<PREP_BLOCKS, 256>>>(x, W1, W2, W3, inW, outW, x16);

    dim3 gH(2, MROWS / 256);   // plain GEMM, N=256
    dim3 gQ(6, MROWS / 256);   // qkv, N=768
    dim3 gM(2, MROWS / 192);   // fused mix GEMM (512 row tiles)

    // 2: gcn1 GEMM + mix + relu -> buf2 (h1)
    k_hgemm_mix<<<gM, 256, M_SMEM>>>(x16, w1, b1, buf2, FIN);

    // 3: gcn2 GEMM + mix + relu -> buf3 (h2, residual)
    k_hgemm_mix<<<gM, 256, M_SMEM>>>(buf2, w2, b2, buf3, HID);

    // 4: qkv GEMM
    k_hgemm<true><<<gQ, 256, SMEM_BYTES>>>(buf3, iw, inB, bufQ, HID, E3);

    // 5: attention -> buf1
    k_attn<<<B_SZ, 128>>>(bufQ, buf1);

    // 6: out_proj GEMM -> buf2
    k_hgemm<true><<<gH, 256, SMEM_BYTES>>>(buf1, ow, outB, buf2, HID, HID);

    // 7: residual + LN -> buf1
    k_ln<<<MROWS / 8, 256>>>(buf3, buf2, lng, lnb, buf1);

    // 8: gcn3 GEMM -> buf2
    k_hgemm<false><<<gH, 256, SMEM_BYTES>>>(buf1, w3, nullptr, buf2, HID, HID);

    // 9: pooling
    k_final<<<B_SZ, 256>>>(buf2, b3, out);
}